// round 13
// baseline (speedup 1.0000x reference)
#include <cuda_runtime.h>
#include <math.h>

#define NF 16          // B*S frames
#define AA 24000
#define CC 80
#define MM 20
#define CE 7
#define TA 240         // anchors per tile (phase 2)
#define TPF 100        // AA/TA
#define TILES (TPF * NF)   // 1600
#define GRID 592       // 148 SMs x 4 resident blocks
#define MGRID 512      // blocks doing phase-1 match (32 per frame)
#define APB 750        // anchors per phase-1 block
#define THREADS 256

// ---- device scratch (.bss zero; finalize resets mutable state for graph replay) ----
__device__ unsigned long long g_gt_key[NF * MM];
__device__ signed char        g_meta[NF * AA];    // signed! aarch64 plain char is unsigned
__device__ unsigned           g_labm[NF * MM * 3];
__device__ float              g_w[CC];
__device__ double             g_cls_sum;
__device__ double             g_reg_sum;
__device__ int                g_pos_cnt;
__device__ unsigned           g_bar;
__device__ unsigned           g_done;

__device__ __forceinline__ float ex2f(float x){ float y; asm("ex2.approx.f32 %0,%1;":"=f"(y):"f"(x)); return y; }
__device__ __forceinline__ float lg2f(float x){ float y; asm("lg2.approx.f32 %0,%1;":"=f"(y):"f"(x)); return y; }

// 1/v for v in [1,2]: linear seed (24/17 - 8/17*v, rel err <= 1/17) + 2 Newton steps
__device__ __forceinline__ float rcp12(float v) {
    float r0 = fmaf(v, -0.470588235294118f, 1.411764705882353f);
    float r1 = fmaf(r0, fmaf(-v, r0, 1.f), r0);
    return fmaf(r1, fmaf(-v, r1, 1.f), r1);
}

__global__ void __launch_bounds__(THREADS, 4)
fused_all(const float* __restrict__ confidence, const float* __restrict__ pred_loc,
          const float* __restrict__ gt_boxes, const float* __restrict__ gt_labels,
          const int* __restrict__ counts, const float* __restrict__ anchors,
          const float* __restrict__ ego_preds, const int* __restrict__ ego_labels,
          const int* __restrict__ cls_num_list, float* __restrict__ out, int out_size) {
    int b = blockIdx.x;
    int tid = threadIdx.x;
    int lane = tid & 31, wrp = tid >> 5;

    __shared__ float4 gtb_s[MM];
    __shared__ float  sga_s[MM];
    __shared__ unsigned long long smkey[MM];
    __shared__ unsigned labm_s[MM * 3];
    __shared__ float  w_s[CC];
    __shared__ signed char meta_s[TA];
    __shared__ int    sidx_s[MM];
    __shared__ float  redc[8], redr[8], redp[8];
    __shared__ float  col_s[CE];
    __shared__ int    nval_s;
    __shared__ int    sflag;
    __shared__ float  sraw[THREADS];

    // ========== PHASE 1: match — single pass, division-free compares ==========
    if (b < MGRID) {
        int f1 = b >> 5;
        int sub = b & 31;
        int base = sub * APB;
        if (tid < MM) {
            float4 bx = ((const float4*)gt_boxes)[f1 * MM + tid];
            gtb_s[tid] = bx;
            sga_s[tid] = (bx.z - bx.x) * (bx.w - bx.y);
            smkey[tid] = 0ull;
        }
        __syncthreads();
        int count1 = counts[f1]; if (count1 > MM) count1 = MM;

        for (int i = tid; i < APB; i += THREADS) {
            int a = base + i;
            float4 an = ((const float4*)anchors)[a];
            float ax1 = an.x - 0.5f * an.z, ay1 = an.y - 0.5f * an.w;
            float ax2 = an.x + 0.5f * an.z, ay2 = an.y + 0.5f * an.w;
            float sa = an.z * an.w;
            float bI = -1.f, bU = 1.f; int aM = 0;   // rational best: q = bI/bU
            for (int m = 0; m < count1; m++) {
                float4 bb = gtb_s[m];
                float lx = fmaxf(ax1, bb.x), ly = fmaxf(ay1, bb.y);
                float rx = fminf(ax2, bb.z), ry = fminf(ay2, bb.w);
                float w = fmaxf(rx - lx, 0.f), h = fmaxf(ry - ly, 0.f);
                float inter = w * h;
                float uni = sa + sga_s[m] - inter;
                // per-anchor best gt: cross-multiplied compare, no division
                if (inter * bU > bI * uni) { bI = inter; bU = uni; aM = m; }
                // per-gt best anchor: guarded shared 64-bit atomicMax
                unsigned hi = ((volatile unsigned*)smkey)[2 * m + 1];
                float ki = __uint_as_float(hi) - 1.f;   // stored (1+q); init 0 -> ki=-1
                if (inter > ki * uni) {
                    float q = inter / (uni + 1e-10f);
                    unsigned long long key =
                        ((unsigned long long)__float_as_uint(1.f + q) << 32) |
                        (unsigned long long)(0xFFFFFFFFu - (unsigned)a);  // smaller idx wins
                    atomicMax(&smkey[m], key);
                }
            }
            int meta = -1;
            if (count1 > 0) {
                float aq = bI / (bU + 1e-10f);          // one divide per anchor
                meta = (aq < 0.4f) ? -2 : ((aq < 0.5f) ? -1 : aM);
            }
            g_meta[f1 * AA + a] = (signed char)meta;
        }
        __syncthreads();
        if (tid < count1) {
            unsigned long long k = smkey[tid];
            if (k) atomicMax(&g_gt_key[f1 * MM + tid], k);
        }
        if (sub == 0) {   // label bitmasks, once per frame
            const float* gl = gt_labels + (size_t)f1 * MM * CC;
            for (int m = wrp; m < MM; m += 8) {
                unsigned b0 = __ballot_sync(0xffffffffu, gl[m * CC + lane] > 0.5f);
                unsigned b1 = __ballot_sync(0xffffffffu, gl[m * CC + 32 + lane] > 0.5f);
                unsigned b2 = __ballot_sync(0xffffffffu, (lane < 16) ? (gl[m * CC + 64 + lane] > 0.5f) : false);
                if (lane == 0) {
                    g_labm[(f1 * MM + m) * 3]     = b0;
                    g_labm[(f1 * MM + m) * 3 + 1] = b1;
                    g_labm[(f1 * MM + m) * 3 + 2] = b2;
                }
            }
        }
        if (b == 0) {     // class-balance weights
            float raw = 0.f;
            if (tid < CC) {
                double beta = (double)0.9999f;
                raw = (float)((1.0 - beta) / (1.0 - pow(beta, (double)cls_num_list[tid])));
            }
            sraw[tid] = raw;
            __syncthreads();
            for (int s = 128; s > 0; s >>= 1) { if (tid < s) sraw[tid] += sraw[tid + s]; __syncthreads(); }
            if (tid < CC) g_w[tid] = raw / sraw[0];
        }
    }

    // ======================= GRID BARRIER =======================
    __threadfence();
    __syncthreads();
    if (tid == 0) {
        atomicAdd(&g_bar, 1u);
        volatile unsigned* vb = &g_bar;
        while (*vb < (unsigned)GRID) __nanosleep(128);
        __threadfence();
    }
    __syncthreads();

    // ======================= PHASE 2: loss =======================
    if (tid < CC) w_s[tid] = __ldcg(&g_w[tid]);
    const float L2E = 1.4426950408889634f;
    const float LN2 = 0.6931471805599453f;
    int a0 = tid / 20;                    // valid for tid<240
    int cb4 = (tid - a0 * 20) * 4;
    int cw = cb4 >> 5, cs = cb4 & 31;
    float accN = 0.f, accPOS = 0.f, accR = 0.f, accP = 0.f;

    for (int tile = b; tile < TILES; tile += GRID) {
        int f = tile / TPF;
        int ab = (tile - f * TPF) * TA;
        __syncthreads();                                 // protect smem reuse
        int count = counts[f]; if (count > MM) count = MM;
        if (tid < MM * 3) labm_s[tid] = __ldcg(&g_labm[f * MM * 3 + tid]);
        if (tid < MM) {
            gtb_s[tid] = ((const float4*)gt_boxes)[f * MM + tid];
            int sidx = -1;
            if (tid < count) {
                unsigned long long key = __ldcg(&g_gt_key[f * MM + tid]);
                sidx = (int)(0xFFFFFFFFu - (unsigned)(key & 0xFFFFFFFFull));
            }
            sidx_s[tid] = sidx;
        }
        int meta = -1;
        if (tid < TA) meta = (int)__ldcg(&g_meta[f * AA + ab + tid]);
        __syncthreads();
        if (tid < TA) {
            int a = ab + tid;
            for (int m = 0; m < count; m++)              // ascending: last wins (ref scatter)
                if (sidx_s[m] == a) meta = m;
            meta_s[tid] = (signed char)meta;
            if (meta >= 0) {
                accP += 1.f;
                float4 an = ((const float4*)anchors)[a];
                float4 bb = gtb_s[meta];
                float lcx = ((bb.x + bb.z) * 0.5f - an.x) / (0.1f * an.z);
                float lcy = ((bb.y + bb.w) * 0.5f - an.y) / (0.1f * an.w);
                float lw = logf(fmaxf(bb.z - bb.x, 1e-6f) / an.z) * 5.0f;
                float lh = logf(fmaxf(bb.w - bb.y, 1e-6f) / an.w) * 5.0f;
                float4 pl = ((const float4*)pred_loc)[f * AA + a];
                float n0 = fabsf(pl.x - lcx), n1 = fabsf(pl.y - lcy);
                float n2 = fabsf(pl.z - lw),  n3 = fabsf(pl.w - lh);
                const float SB = 1.f / 9.f;
                accR += (n0 < SB ? 4.5f * n0 * n0 : n0 - 0.5f * SB);
                accR += (n1 < SB ? 4.5f * n1 * n1 : n1 - 0.5f * SB);
                accR += (n2 < SB ? 4.5f * n2 * n2 : n2 - 0.5f * SB);
                accR += (n3 < SB ? 4.5f * n3 * n3 : n3 - 0.5f * SB);
            }
        }
        __syncthreads();

        // ---- hot loop: 5 batches x 4 unconditional loads, 2-MUFU focal math ----
        // t=x*log2e, u=2^(-|t|), v=1+u in [1,2], s=lg2(v), r=1/v via FMA-Newton.
        // softplus(x)/ln2 = s+max(t,0);  sigmoid(x) = (t>0 ? r : u*r)
        // neg: ln2*(s+max(t,0))*sigmoid(x)*1e-4
        // pos: w*ln2*(s-min(t,0))*(t>0 ? u*r : r)
        if (count > 0 && tid < 240) {
            const float4* c4 = (const float4*)(confidence + ((size_t)f * AA + ab) * CC) + tid;
            for (int blk = 0; blk < 5; blk++) {
                int it0 = blk * 4;
                float4 x0 = __ldcs(c4 + (it0 + 0) * 240);
                float4 x1 = __ldcs(c4 + (it0 + 1) * 240);
                float4 x2 = __ldcs(c4 + (it0 + 2) * 240);
                float4 x3 = __ldcs(c4 + (it0 + 3) * 240);
                float4 xb[4] = {x0, x1, x2, x3};
#pragma unroll
                for (int j = 0; j < 4; j++) {
                    int m = (int)meta_s[(it0 + j) * 12 + a0];
                    if (m != -1) {
                        float xs[4] = {xb[j].x, xb[j].y, xb[j].z, xb[j].w};
                        if (m < 0) {    // background fast path (all y=0)
#pragma unroll
                            for (int q = 0; q < 4; q++) {
                                float t = xs[q] * L2E;
                                float u = ex2f(-fabsf(t));
                                float v = 1.f + u;
                                float s = lg2f(v);
                                float r = rcp12(v);
                                float sig = (t > 0.f) ? r : u * r;
                                accN = fmaf(s + fmaxf(t, 0.f), sig, accN);
                            }
                        } else {        // positive anchor (rare)
                            unsigned mb = (labm_s[m * 3 + cw] >> cs) & 0xFu;
#pragma unroll
                            for (int q = 0; q < 4; q++) {
                                float t = xs[q] * L2E;
                                float u = ex2f(-fabsf(t));
                                float v = 1.f + u;
                                float s = lg2f(v);
                                float r = rcp12(v);
                                float sig  = (t > 0.f) ? r : u * r;       // sigmoid(x)
                                float sigm = (t > 0.f) ? u * r : r;       // sigmoid(-x)
                                if ((mb >> q) & 1) accPOS = fmaf(w_s[cb4 + q] * (s - fminf(t, 0.f)), sigm, accPOS);
                                else               accN   = fmaf(s + fmaxf(t, 0.f), sig, accN);
                            }
                        }
                    }
                }
            }
        }
    }

    // ---- block reduce + atomics ----
    const float CB1M = 1.0f - 0.9999f;
    float csum = LN2 * fmaf(CB1M, accN, accPOS);
#pragma unroll
    for (int o = 16; o > 0; o >>= 1) {
        csum += __shfl_down_sync(0xffffffffu, csum, o);
        accR += __shfl_down_sync(0xffffffffu, accR, o);
        accP += __shfl_down_sync(0xffffffffu, accP, o);
    }
    if (lane == 0) { redc[wrp] = csum; redr[wrp] = accR; redp[wrp] = accP; }
    __syncthreads();
    if (tid == 0) {
        float c = 0.f, r = 0.f, p = 0.f;
#pragma unroll
        for (int w = 0; w < 8; w++) { c += redc[w]; r += redr[w]; p += redp[w]; }
        atomicAdd(&g_cls_sum, (double)c);
        if (r != 0.f) atomicAdd(&g_reg_sum, (double)r);
        if (p != 0.f) atomicAdd(&g_pos_cnt, (int)(p + 0.5f));
    }

    // ---- last-block finalize: ego focal + output + state reset ----
    __threadfence();
    if (tid == 0) {
        unsigned d = atomicAdd(&g_done, 1u);
        sflag = (d == (unsigned)(GRID - 1));
    }
    __syncthreads();
    if (sflag) {
        if (tid < CE) col_s[tid] = 0.f;
        if (tid == 0) nval_s = 0;
        __syncthreads();
        if (tid < NF) {
            int l = ego_labels[tid];
            if (l > -1) { atomicAdd(&nval_s, 1); if (l < CE) col_s[l] = 1.f; }
        }
        __syncthreads();
        float term = 0.f;
        if (tid < NF * CE) {
            int i = tid / CE, c = tid - i * CE;
            if (ego_labels[i] > -1) {
                float x = ego_preds[tid];
                float ep = 1.f / (1.f + expf(-x));
                ep = fminf(fmaxf(ep, 1e-7f), 1.f - 1e-7f);
                float oh = col_s[c];
                float af = 0.25f * oh + 0.75f * (1.f - oh);
                float pt = ep * oh + (1.f - ep) * (1.f - oh);
                float bce = -(oh * logf(ep) + (1.f - oh) * log1pf(-ep));
                float omp = 1.f - pt;
                term = bce * af * omp * omp;
            }
        }
#pragma unroll
        for (int o = 16; o > 0; o >>= 1) term += __shfl_down_sync(0xffffffffu, term, o);
        if (lane == 0) redc[wrp] = term;
        __syncthreads();
        if (tid == 0) {
            float esum = redc[0] + redc[1] + redc[2] + redc[3];
            int nval = nval_s;
            float ego = (nval > 0) ? esum / fmaxf((float)nval, 1.f) : 0.f;
            double cs = *((volatile double*)&g_cls_sum);
            double rs = *((volatile double*)&g_reg_sum);
            int pc = *((volatile int*)&g_pos_cnt);
            float np = fmaxf(1.f, (float)pc);
            if (out_size > 0) out[0] = (float)rs / (np * 4.f);
            if (out_size > 1) out[1] = ((float)cs / np) * 0.125f + ego * 0.25f;
            g_cls_sum = 0.0;
            g_reg_sum = 0.0;
            g_pos_cnt = 0;
            g_bar = 0u;
        }
        for (int i = tid; i < NF * MM; i += THREADS) g_gt_key[i] = 0ull;
        __syncthreads();
        if (tid == 0) { __threadfence(); g_done = 0u; }
    }
}

extern "C" void kernel_launch(void* const* d_in, const int* in_sizes, int n_in,
                              void* d_out, int out_size) {
    (void)in_sizes; (void)n_in;
    const float* confidence   = (const float*)d_in[0];
    const float* pred_loc     = (const float*)d_in[1];
    const float* gt_boxes     = (const float*)d_in[2];
    const float* gt_labels    = (const float*)d_in[3];
    const int*   counts       = (const int*)d_in[4];
    const float* anchors      = (const float*)d_in[5];
    const float* ego_preds    = (const float*)d_in[6];
    const int*   ego_labels   = (const int*)d_in[7];
    const int*   cls_num_list = (const int*)d_in[8];
    float* out = (float*)d_out;

    fused_all<<<GRID, THREADS>>>(confidence, pred_loc, gt_boxes, gt_labels, counts,
                                 anchors, ego_preds, ego_labels, cls_num_list, out, out_size);
}

// round 14
// speedup vs baseline: 1.0117x; 1.0117x over previous
#include <cuda_runtime.h>
#include <math.h>

#define NF 16          // B*S frames
#define AA 24000
#define CC 80
#define MM 20
#define CE 7
#define TA 240         // anchors per tile (phase 2)
#define TPF 100        // AA/TA
#define TILES (TPF * NF)   // 1600
#define GRID 592       // 148 SMs x 4 resident blocks
#define MGRID 512      // blocks doing phase-1 match (32 per frame)
#define APB 750        // anchors per phase-1 block
#define THREADS 256

// ---- device scratch (.bss zero; finalize resets mutable state for graph replay) ----
__device__ unsigned long long g_gt_key[NF * MM];
__device__ signed char        g_meta[NF * AA];    // signed! aarch64 plain char is unsigned
__device__ unsigned           g_labm[NF * MM * 3];
__device__ float              g_w[CC];
__device__ double             g_cls_sum;
__device__ double             g_reg_sum;
__device__ int                g_pos_cnt;
__device__ unsigned           g_bar;
__device__ unsigned           g_tile;
__device__ unsigned           g_done;

__device__ __forceinline__ float ex2f(float x){ float y; asm("ex2.approx.f32 %0,%1;":"=f"(y):"f"(x)); return y; }
__device__ __forceinline__ float lg2f(float x){ float y; asm("lg2.approx.f32 %0,%1;":"=f"(y):"f"(x)); return y; }
__device__ __forceinline__ float rcpf(float x){ float y; asm("rcp.approx.f32 %0,%1;":"=f"(y):"f"(x)); return y; }

__global__ void __launch_bounds__(THREADS, 4)
fused_all(const float* __restrict__ confidence, const float* __restrict__ pred_loc,
          const float* __restrict__ gt_boxes, const float* __restrict__ gt_labels,
          const int* __restrict__ counts, const float* __restrict__ anchors,
          const float* __restrict__ ego_preds, const int* __restrict__ ego_labels,
          const int* __restrict__ cls_num_list, float* __restrict__ out, int out_size) {
    int b = blockIdx.x;
    int tid = threadIdx.x;
    int lane = tid & 31, wrp = tid >> 5;

    __shared__ float4 gtb_s[MM];
    __shared__ float  sga_s[MM];
    __shared__ unsigned long long smkey[MM];
    __shared__ unsigned labm_s[MM * 3];
    __shared__ float  w_s[CC];
    __shared__ signed char meta_s[TA];
    __shared__ int    sidx_s[MM];
    __shared__ float  redc[8], redr[8], redp[8];
    __shared__ float  col_s[CE];
    __shared__ int    nval_s;
    __shared__ int    sflag;
    __shared__ int    stile;
    __shared__ float  sraw[THREADS];

    // ========== PHASE 1: match — single pass, division-free compares ==========
    if (b < MGRID) {
        int f1 = b >> 5;
        int sub = b & 31;
        int base = sub * APB;
        if (tid < MM) {
            float4 bx = ((const float4*)gt_boxes)[f1 * MM + tid];
            gtb_s[tid] = bx;
            sga_s[tid] = (bx.z - bx.x) * (bx.w - bx.y);
            smkey[tid] = 0ull;
        }
        __syncthreads();
        int count1 = counts[f1]; if (count1 > MM) count1 = MM;

        for (int i = tid; i < APB; i += THREADS) {
            int a = base + i;
            float4 an = ((const float4*)anchors)[a];
            float ax1 = an.x - 0.5f * an.z, ay1 = an.y - 0.5f * an.w;
            float ax2 = an.x + 0.5f * an.z, ay2 = an.y + 0.5f * an.w;
            float sa = an.z * an.w;
            float bI = -1.f, bU = 1.f; int aM = 0;   // rational best: q = bI/bU
            for (int m = 0; m < count1; m++) {
                float4 bb = gtb_s[m];
                float lx = fmaxf(ax1, bb.x), ly = fmaxf(ay1, bb.y);
                float rx = fminf(ax2, bb.z), ry = fminf(ay2, bb.w);
                float w = fmaxf(rx - lx, 0.f), h = fmaxf(ry - ly, 0.f);
                float inter = w * h;
                float uni = sa + sga_s[m] - inter;
                // per-anchor best gt: cross-multiplied compare, no division
                if (inter * bU > bI * uni) { bI = inter; bU = uni; aM = m; }
                // per-gt best anchor: guarded shared 64-bit atomicMax
                unsigned hi = ((volatile unsigned*)smkey)[2 * m + 1];
                float ki = __uint_as_float(hi) - 1.f;   // stored (1+q); init 0 -> ki=-1
                if (inter > ki * uni) {
                    float q = inter / (uni + 1e-10f);
                    unsigned long long key =
                        ((unsigned long long)__float_as_uint(1.f + q) << 32) |
                        (unsigned long long)(0xFFFFFFFFu - (unsigned)a);  // smaller idx wins
                    atomicMax(&smkey[m], key);
                }
            }
            int meta = -1;
            if (count1 > 0) {
                float aq = bI / (bU + 1e-10f);          // one divide per anchor
                meta = (aq < 0.4f) ? -2 : ((aq < 0.5f) ? -1 : aM);
            }
            g_meta[f1 * AA + a] = (signed char)meta;
        }
        __syncthreads();
        if (tid < count1) {
            unsigned long long k = smkey[tid];
            if (k) atomicMax(&g_gt_key[f1 * MM + tid], k);
        }
        if (sub == 0) {   // label bitmasks, once per frame
            const float* gl = gt_labels + (size_t)f1 * MM * CC;
            for (int m = wrp; m < MM; m += 8) {
                unsigned b0 = __ballot_sync(0xffffffffu, gl[m * CC + lane] > 0.5f);
                unsigned b1 = __ballot_sync(0xffffffffu, gl[m * CC + 32 + lane] > 0.5f);
                unsigned b2 = __ballot_sync(0xffffffffu, (lane < 16) ? (gl[m * CC + 64 + lane] > 0.5f) : false);
                if (lane == 0) {
                    g_labm[(f1 * MM + m) * 3]     = b0;
                    g_labm[(f1 * MM + m) * 3 + 1] = b1;
                    g_labm[(f1 * MM + m) * 3 + 2] = b2;
                }
            }
        }
        if (b == 0) {     // class-balance weights
            float raw = 0.f;
            if (tid < CC) {
                double beta = (double)0.9999f;
                raw = (float)((1.0 - beta) / (1.0 - pow(beta, (double)cls_num_list[tid])));
            }
            sraw[tid] = raw;
            __syncthreads();
            for (int s = 128; s > 0; s >>= 1) { if (tid < s) sraw[tid] += sraw[tid + s]; __syncthreads(); }
            if (tid < CC) g_w[tid] = raw / sraw[0];
        }
    }

    // ======================= GRID BARRIER =======================
    __threadfence();
    __syncthreads();
    if (tid == 0) {
        atomicAdd(&g_bar, 1u);
        volatile unsigned* vb = &g_bar;
        while (*vb < (unsigned)GRID) __nanosleep(64);
        __threadfence();
    }
    __syncthreads();

    // ======================= PHASE 2: loss (dynamic tile stealing) =======================
    if (tid < CC) w_s[tid] = __ldcg(&g_w[tid]);
    const float L2E = 1.4426950408889634f;
    const float LN2 = 0.6931471805599453f;
    int a0 = tid / 20;                    // valid for tid<240
    int cb4 = (tid - a0 * 20) * 4;
    int cw = cb4 >> 5, cs = cb4 & 31;
    float accN = 0.f, accPOS = 0.f, accR = 0.f, accP = 0.f;

    for (;;) {
        __syncthreads();                                 // protect smem reuse across iterations
        if (tid == 0) stile = (int)atomicAdd(&g_tile, 1u);
        __syncthreads();
        int tile = stile;
        if (tile >= TILES) break;
        int f = tile / TPF;
        int ab = (tile - f * TPF) * TA;
        int count = counts[f]; if (count > MM) count = MM;
        if (tid < MM * 3) labm_s[tid] = __ldcg(&g_labm[f * MM * 3 + tid]);
        if (tid < MM) {
            gtb_s[tid] = ((const float4*)gt_boxes)[f * MM + tid];
            int sidx = -1;
            if (tid < count) {
                unsigned long long key = __ldcg(&g_gt_key[f * MM + tid]);
                sidx = (int)(0xFFFFFFFFu - (unsigned)(key & 0xFFFFFFFFull));
            }
            sidx_s[tid] = sidx;
        }
        int meta = -1;
        if (tid < TA) meta = (int)__ldcg(&g_meta[f * AA + ab + tid]);
        __syncthreads();
        if (tid < TA) {
            int a = ab + tid;
            for (int m = 0; m < count; m++)              // ascending: last wins (ref scatter)
                if (sidx_s[m] == a) meta = m;
            meta_s[tid] = (signed char)meta;
            if (meta >= 0) {
                accP += 1.f;
                float4 an = ((const float4*)anchors)[a];
                float4 bb = gtb_s[meta];
                float lcx = ((bb.x + bb.z) * 0.5f - an.x) / (0.1f * an.z);
                float lcy = ((bb.y + bb.w) * 0.5f - an.y) / (0.1f * an.w);
                float lw = logf(fmaxf(bb.z - bb.x, 1e-6f) / an.z) * 5.0f;
                float lh = logf(fmaxf(bb.w - bb.y, 1e-6f) / an.w) * 5.0f;
                float4 pl = ((const float4*)pred_loc)[f * AA + a];
                float n0 = fabsf(pl.x - lcx), n1 = fabsf(pl.y - lcy);
                float n2 = fabsf(pl.z - lw),  n3 = fabsf(pl.w - lh);
                const float SB = 1.f / 9.f;
                accR += (n0 < SB ? 4.5f * n0 * n0 : n0 - 0.5f * SB);
                accR += (n1 < SB ? 4.5f * n1 * n1 : n1 - 0.5f * SB);
                accR += (n2 < SB ? 4.5f * n2 * n2 : n2 - 0.5f * SB);
                accR += (n3 < SB ? 4.5f * n3 * n3 : n3 - 0.5f * SB);
            }
        }
        __syncthreads();

        // ---- per-thread meta masks: one LDS burst, register-bit tests in hot loop ----
        unsigned mProc = 0u, mPos = 0u;
        if (tid < 240) {
#pragma unroll
            for (int it = 0; it < 20; it++) {
                int mm = (int)meta_s[it * 12 + a0];
                mProc |= (unsigned)(mm != -1) << it;
                mPos  |= (unsigned)(mm >= 0) << it;
            }
        }

        // ---- hot loop: 5 batches x 4 unconditional loads, 3-MUFU math, no LDS for bg ----
        //   t=x*log2e, u=2^t, v=1+u, s=lg2(v), r=1/v
        //   neg: ln2*s*(1-r)*1e-4     pos: w*ln2*(s-t)*r
        if (count > 0 && tid < 240) {
            const float4* c4 = (const float4*)(confidence + ((size_t)f * AA + ab) * CC) + tid;
            for (int blk = 0; blk < 5; blk++) {
                int it0 = blk * 4;
                float4 x0 = __ldcs(c4 + (it0 + 0) * 240);
                float4 x1 = __ldcs(c4 + (it0 + 1) * 240);
                float4 x2 = __ldcs(c4 + (it0 + 2) * 240);
                float4 x3 = __ldcs(c4 + (it0 + 3) * 240);
                float4 xb[4] = {x0, x1, x2, x3};
#pragma unroll
                for (int j = 0; j < 4; j++) {
                    int idx = it0 + j;
                    if ((mProc >> idx) & 1) {
                        float xs[4] = {xb[j].x, xb[j].y, xb[j].z, xb[j].w};
                        if (!((mPos >> idx) & 1)) {    // background fast path (all y=0)
#pragma unroll
                            for (int q = 0; q < 4; q++) {
                                float t = xs[q] * L2E;
                                float v = 1.f + ex2f(t);
                                float s = lg2f(v);
                                accN = fmaf(s, 1.f - rcpf(v), accN);
                            }
                        } else {                        // positive anchor (rare)
                            int m = (int)meta_s[idx * 12 + a0];
                            unsigned mb = (labm_s[m * 3 + cw] >> cs) & 0xFu;
#pragma unroll
                            for (int q = 0; q < 4; q++) {
                                float t = xs[q] * L2E;
                                float v = 1.f + ex2f(t);
                                float s = lg2f(v);
                                float r = rcpf(v);
                                if ((mb >> q) & 1) accPOS = fmaf(w_s[cb4 + q] * (s - t), r, accPOS);
                                else               accN   = fmaf(s, 1.f - r, accN);
                            }
                        }
                    }
                }
            }
        }
    }

    // ---- block reduce + atomics ----
    const float CB1M = 1.0f - 0.9999f;
    float csum = LN2 * fmaf(CB1M, accN, accPOS);
#pragma unroll
    for (int o = 16; o > 0; o >>= 1) {
        csum += __shfl_down_sync(0xffffffffu, csum, o);
        accR += __shfl_down_sync(0xffffffffu, accR, o);
        accP += __shfl_down_sync(0xffffffffu, accP, o);
    }
    if (lane == 0) { redc[wrp] = csum; redr[wrp] = accR; redp[wrp] = accP; }
    __syncthreads();
    if (tid == 0) {
        float c = 0.f, r = 0.f, p = 0.f;
#pragma unroll
        for (int w = 0; w < 8; w++) { c += redc[w]; r += redr[w]; p += redp[w]; }
        atomicAdd(&g_cls_sum, (double)c);
        if (r != 0.f) atomicAdd(&g_reg_sum, (double)r);
        if (p != 0.f) atomicAdd(&g_pos_cnt, (int)(p + 0.5f));
    }

    // ---- last-block finalize: ego focal + output + state reset ----
    __threadfence();
    if (tid == 0) {
        unsigned d = atomicAdd(&g_done, 1u);
        sflag = (d == (unsigned)(GRID - 1));
    }
    __syncthreads();
    if (sflag) {
        if (tid < CE) col_s[tid] = 0.f;
        if (tid == 0) nval_s = 0;
        __syncthreads();
        if (tid < NF) {
            int l = ego_labels[tid];
            if (l > -1) { atomicAdd(&nval_s, 1); if (l < CE) col_s[l] = 1.f; }
        }
        __syncthreads();
        float term = 0.f;
        if (tid < NF * CE) {
            int i = tid / CE, c = tid - i * CE;
            if (ego_labels[i] > -1) {
                float x = ego_preds[tid];
                float ep = 1.f / (1.f + expf(-x));
                ep = fminf(fmaxf(ep, 1e-7f), 1.f - 1e-7f);
                float oh = col_s[c];
                float af = 0.25f * oh + 0.75f * (1.f - oh);
                float pt = ep * oh + (1.f - ep) * (1.f - oh);
                float bce = -(oh * logf(ep) + (1.f - oh) * log1pf(-ep));
                float omp = 1.f - pt;
                term = bce * af * omp * omp;
            }
        }
#pragma unroll
        for (int o = 16; o > 0; o >>= 1) term += __shfl_down_sync(0xffffffffu, term, o);
        if (lane == 0) redc[wrp] = term;
        __syncthreads();
        if (tid == 0) {
            float esum = redc[0] + redc[1] + redc[2] + redc[3];
            int nval = nval_s;
            float ego = (nval > 0) ? esum / fmaxf((float)nval, 1.f) : 0.f;
            double cs = *((volatile double*)&g_cls_sum);
            double rs = *((volatile double*)&g_reg_sum);
            int pc = *((volatile int*)&g_pos_cnt);
            float np = fmaxf(1.f, (float)pc);
            if (out_size > 0) out[0] = (float)rs / (np * 4.f);
            if (out_size > 1) out[1] = ((float)cs / np) * 0.125f + ego * 0.25f;
            g_cls_sum = 0.0;
            g_reg_sum = 0.0;
            g_pos_cnt = 0;
            g_bar = 0u;
            g_tile = 0u;
        }
        for (int i = tid; i < NF * MM; i += THREADS) g_gt_key[i] = 0ull;
        __syncthreads();
        if (tid == 0) { __threadfence(); g_done = 0u; }
    }
}

extern "C" void kernel_launch(void* const* d_in, const int* in_sizes, int n_in,
                              void* d_out, int out_size) {
    (void)in_sizes; (void)n_in;
    const float* confidence   = (const float*)d_in[0];
    const float* pred_loc     = (const float*)d_in[1];
    const float* gt_boxes     = (const float*)d_in[2];
    const float* gt_labels    = (const float*)d_in[3];
    const int*   counts       = (const int*)d_in[4];
    const float* anchors      = (const float*)d_in[5];
    const float* ego_preds    = (const float*)d_in[6];
    const int*   ego_labels   = (const int*)d_in[7];
    const int*   cls_num_list = (const int*)d_in[8];
    float* out = (float*)d_out;

    fused_all<<<GRID, THREADS>>>(confidence, pred_loc, gt_boxes, gt_labels, counts,
                                 anchors, ego_preds, ego_labels, cls_num_list, out, out_size);
}

// round 15
// speedup vs baseline: 1.0810x; 1.0685x over previous
#include <cuda_runtime.h>
#include <math.h>

#define NF 16          // B*S frames
#define AA 24000
#define CC 80
#define MM 20
#define CE 7
#define TA 240         // anchors per tile (phase 2)
#define TPF 100        // AA/TA
#define TILES (TPF * NF)   // 1600
#define GRID 740       // 148 SMs x 5 resident blocks
#define MGRID 512      // blocks doing phase-1 match (32 per frame)
#define APB 750        // anchors per phase-1 block
#define THREADS 256

// ---- device scratch (.bss zero; finalize resets mutable state for graph replay) ----
__device__ unsigned long long g_gt_key[NF * MM];
__device__ signed char        g_meta[NF * AA];    // signed! aarch64 plain char is unsigned
__device__ unsigned           g_labm[NF * MM * 3];
__device__ float              g_w[CC];
__device__ double             g_cls_sum;
__device__ double             g_reg_sum;
__device__ int                g_pos_cnt;
__device__ unsigned           g_bar;
__device__ unsigned           g_tile;
__device__ unsigned           g_done;

__device__ __forceinline__ float ex2f(float x){ float y; asm("ex2.approx.f32 %0,%1;":"=f"(y):"f"(x)); return y; }
__device__ __forceinline__ float lg2f(float x){ float y; asm("lg2.approx.f32 %0,%1;":"=f"(y):"f"(x)); return y; }
__device__ __forceinline__ float rcpf(float x){ float y; asm("rcp.approx.f32 %0,%1;":"=f"(y):"f"(x)); return y; }

__global__ void __launch_bounds__(THREADS, 5)
fused_all(const float* __restrict__ confidence, const float* __restrict__ pred_loc,
          const float* __restrict__ gt_boxes, const float* __restrict__ gt_labels,
          const int* __restrict__ counts, const float* __restrict__ anchors,
          const float* __restrict__ ego_preds, const int* __restrict__ ego_labels,
          const int* __restrict__ cls_num_list, float* __restrict__ out, int out_size) {
    int b = blockIdx.x;
    int tid = threadIdx.x;
    int lane = tid & 31, wrp = tid >> 5;

    __shared__ float4 gtb_s[MM];
    __shared__ float  sga_s[MM];
    __shared__ unsigned long long smkey[MM];
    __shared__ unsigned labm_s[MM * 3];
    __shared__ float  w_s[CC];
    __shared__ signed char meta_s[TA];
    __shared__ int    sidx_s[MM];
    __shared__ float  redc[8], redr[8], redp[8];
    __shared__ float  col_s[CE];
    __shared__ int    nval_s;
    __shared__ int    sflag;
    __shared__ int    stile;
    __shared__ float  sraw[THREADS];

    // ========== PHASE 1: match — single pass, division-free compares ==========
    if (b < MGRID) {
        int f1 = b >> 5;
        int sub = b & 31;
        int base = sub * APB;
        if (tid < MM) {
            float4 bx = ((const float4*)gt_boxes)[f1 * MM + tid];
            gtb_s[tid] = bx;
            sga_s[tid] = (bx.z - bx.x) * (bx.w - bx.y);
            smkey[tid] = 0ull;
        }
        __syncthreads();
        int count1 = counts[f1]; if (count1 > MM) count1 = MM;

        for (int i = tid; i < APB; i += THREADS) {
            int a = base + i;
            float4 an = ((const float4*)anchors)[a];
            float ax1 = an.x - 0.5f * an.z, ay1 = an.y - 0.5f * an.w;
            float ax2 = an.x + 0.5f * an.z, ay2 = an.y + 0.5f * an.w;
            float sa = an.z * an.w;
            float bI = -1.f, bU = 1.f; int aM = 0;   // rational best: q = bI/bU
            for (int m = 0; m < count1; m++) {
                float4 bb = gtb_s[m];
                float lx = fmaxf(ax1, bb.x), ly = fmaxf(ay1, bb.y);
                float rx = fminf(ax2, bb.z), ry = fminf(ay2, bb.w);
                float w = fmaxf(rx - lx, 0.f), h = fmaxf(ry - ly, 0.f);
                float inter = w * h;
                float uni = sa + sga_s[m] - inter;
                // per-anchor best gt: cross-multiplied compare, no division
                if (inter * bU > bI * uni) { bI = inter; bU = uni; aM = m; }
                // per-gt best anchor: guarded shared 64-bit atomicMax
                unsigned hi = ((volatile unsigned*)smkey)[2 * m + 1];
                float ki = __uint_as_float(hi) - 1.f;   // stored (1+q); init 0 -> ki=-1
                if (inter > ki * uni) {
                    float q = inter / (uni + 1e-10f);
                    unsigned long long key =
                        ((unsigned long long)__float_as_uint(1.f + q) << 32) |
                        (unsigned long long)(0xFFFFFFFFu - (unsigned)a);  // smaller idx wins
                    atomicMax(&smkey[m], key);
                }
            }
            int meta = -1;
            if (count1 > 0) {
                float aq = bI / (bU + 1e-10f);          // one divide per anchor
                meta = (aq < 0.4f) ? -2 : ((aq < 0.5f) ? -1 : aM);
            }
            g_meta[f1 * AA + a] = (signed char)meta;
        }
        __syncthreads();
        if (tid < count1) {
            unsigned long long k = smkey[tid];
            if (k) atomicMax(&g_gt_key[f1 * MM + tid], k);
        }
        if (sub == 0) {   // label bitmasks, once per frame
            const float* gl = gt_labels + (size_t)f1 * MM * CC;
            for (int m = wrp; m < MM; m += 8) {
                unsigned b0 = __ballot_sync(0xffffffffu, gl[m * CC + lane] > 0.5f);
                unsigned b1 = __ballot_sync(0xffffffffu, gl[m * CC + 32 + lane] > 0.5f);
                unsigned b2 = __ballot_sync(0xffffffffu, (lane < 16) ? (gl[m * CC + 64 + lane] > 0.5f) : false);
                if (lane == 0) {
                    g_labm[(f1 * MM + m) * 3]     = b0;
                    g_labm[(f1 * MM + m) * 3 + 1] = b1;
                    g_labm[(f1 * MM + m) * 3 + 2] = b2;
                }
            }
        }
        if (b == 0) {     // class-balance weights
            float raw = 0.f;
            if (tid < CC) {
                double beta = (double)0.9999f;
                raw = (float)((1.0 - beta) / (1.0 - pow(beta, (double)cls_num_list[tid])));
            }
            sraw[tid] = raw;
            __syncthreads();
            for (int s = 128; s > 0; s >>= 1) { if (tid < s) sraw[tid] += sraw[tid + s]; __syncthreads(); }
            if (tid < CC) g_w[tid] = raw / sraw[0];
        }
    }

    // ======================= GRID BARRIER =======================
    __threadfence();
    __syncthreads();
    if (tid == 0) {
        atomicAdd(&g_bar, 1u);
        volatile unsigned* vb = &g_bar;
        while (*vb < (unsigned)GRID) __nanosleep(64);
        __threadfence();
    }
    __syncthreads();

    // ======================= PHASE 2: loss (dynamic tile stealing) =======================
    if (tid < CC) w_s[tid] = __ldcg(&g_w[tid]);
    const float L2E = 1.4426950408889634f;
    const float LN2 = 0.6931471805599453f;
    int a0 = tid / 20;                    // valid for tid<240
    int cb4 = (tid - a0 * 20) * 4;
    int cw = cb4 >> 5, cs = cb4 & 31;
    float accN = 0.f, accPOS = 0.f, accR = 0.f, accP = 0.f;

    for (;;) {
        __syncthreads();                                 // protect smem reuse across iterations
        if (tid == 0) stile = (int)atomicAdd(&g_tile, 1u);
        __syncthreads();
        int tile = stile;
        if (tile >= TILES) break;
        int f = tile / TPF;
        int ab = (tile - f * TPF) * TA;
        int count = counts[f]; if (count > MM) count = MM;
        if (tid < MM * 3) labm_s[tid] = __ldcg(&g_labm[f * MM * 3 + tid]);
        if (tid < MM) {
            gtb_s[tid] = ((const float4*)gt_boxes)[f * MM + tid];
            int sidx = -1;
            if (tid < count) {
                unsigned long long key = __ldcg(&g_gt_key[f * MM + tid]);
                sidx = (int)(0xFFFFFFFFu - (unsigned)(key & 0xFFFFFFFFull));
            }
            sidx_s[tid] = sidx;
        }
        int meta = -1;
        if (tid < TA) meta = (int)__ldcg(&g_meta[f * AA + ab + tid]);
        __syncthreads();
        if (tid < TA) {
            int a = ab + tid;
            for (int m = 0; m < count; m++)              // ascending: last wins (ref scatter)
                if (sidx_s[m] == a) meta = m;
            meta_s[tid] = (signed char)meta;
            if (meta >= 0) {
                accP += 1.f;
                float4 an = ((const float4*)anchors)[a];
                float4 bb = gtb_s[meta];
                float lcx = ((bb.x + bb.z) * 0.5f - an.x) / (0.1f * an.z);
                float lcy = ((bb.y + bb.w) * 0.5f - an.y) / (0.1f * an.w);
                float lw = logf(fmaxf(bb.z - bb.x, 1e-6f) / an.z) * 5.0f;
                float lh = logf(fmaxf(bb.w - bb.y, 1e-6f) / an.w) * 5.0f;
                float4 pl = ((const float4*)pred_loc)[f * AA + a];
                float n0 = fabsf(pl.x - lcx), n1 = fabsf(pl.y - lcy);
                float n2 = fabsf(pl.z - lw),  n3 = fabsf(pl.w - lh);
                const float SB = 1.f / 9.f;
                accR += (n0 < SB ? 4.5f * n0 * n0 : n0 - 0.5f * SB);
                accR += (n1 < SB ? 4.5f * n1 * n1 : n1 - 0.5f * SB);
                accR += (n2 < SB ? 4.5f * n2 * n2 : n2 - 0.5f * SB);
                accR += (n3 < SB ? 4.5f * n3 * n3 : n3 - 0.5f * SB);
            }
        }
        __syncthreads();

        // ---- hot loop: 5 batches x 4 unconditional loads, 3-MUFU math ----
        //   t=x*log2e, u=2^t, v=1+u, s=lg2(v), r=1/v
        //   neg: ln2*s*(1-r)*1e-4     pos: w*ln2*(s-t)*r
        if (count > 0 && tid < 240) {
            const float4* c4 = (const float4*)(confidence + ((size_t)f * AA + ab) * CC) + tid;
            for (int blk = 0; blk < 5; blk++) {
                int it0 = blk * 4;
                float4 x0 = __ldcs(c4 + (it0 + 0) * 240);
                float4 x1 = __ldcs(c4 + (it0 + 1) * 240);
                float4 x2 = __ldcs(c4 + (it0 + 2) * 240);
                float4 x3 = __ldcs(c4 + (it0 + 3) * 240);
                float4 xb[4] = {x0, x1, x2, x3};
#pragma unroll
                for (int j = 0; j < 4; j++) {
                    int m = (int)meta_s[(it0 + j) * 12 + a0];
                    if (m != -1) {
                        float xs[4] = {xb[j].x, xb[j].y, xb[j].z, xb[j].w};
                        if (m < 0) {    // background fast path (all y=0)
#pragma unroll
                            for (int q = 0; q < 4; q++) {
                                float t = xs[q] * L2E;
                                float v = 1.f + ex2f(t);
                                float s = lg2f(v);
                                accN = fmaf(s, 1.f - rcpf(v), accN);
                            }
                        } else {        // positive anchor (rare)
                            unsigned mb = (labm_s[m * 3 + cw] >> cs) & 0xFu;
#pragma unroll
                            for (int q = 0; q < 4; q++) {
                                float t = xs[q] * L2E;
                                float v = 1.f + ex2f(t);
                                float s = lg2f(v);
                                float r = rcpf(v);
                                if ((mb >> q) & 1) accPOS = fmaf(w_s[cb4 + q] * (s - t), r, accPOS);
                                else               accN   = fmaf(s, 1.f - r, accN);
                            }
                        }
                    }
                }
            }
        }
    }

    // ---- block reduce + atomics ----
    const float CB1M = 1.0f - 0.9999f;
    float csum = LN2 * fmaf(CB1M, accN, accPOS);
#pragma unroll
    for (int o = 16; o > 0; o >>= 1) {
        csum += __shfl_down_sync(0xffffffffu, csum, o);
        accR += __shfl_down_sync(0xffffffffu, accR, o);
        accP += __shfl_down_sync(0xffffffffu, accP, o);
    }
    if (lane == 0) { redc[wrp] = csum; redr[wrp] = accR; redp[wrp] = accP; }
    __syncthreads();
    if (tid == 0) {
        float c = 0.f, r = 0.f, p = 0.f;
#pragma unroll
        for (int w = 0; w < 8; w++) { c += redc[w]; r += redr[w]; p += redp[w]; }
        atomicAdd(&g_cls_sum, (double)c);
        if (r != 0.f) atomicAdd(&g_reg_sum, (double)r);
        if (p != 0.f) atomicAdd(&g_pos_cnt, (int)(p + 0.5f));
    }

    // ---- last-block finalize: ego focal + output + state reset ----
    __threadfence();
    if (tid == 0) {
        unsigned d = atomicAdd(&g_done, 1u);
        sflag = (d == (unsigned)(GRID - 1));
    }
    __syncthreads();
    if (sflag) {
        if (tid < CE) col_s[tid] = 0.f;
        if (tid == 0) nval_s = 0;
        __syncthreads();
        if (tid < NF) {
            int l = ego_labels[tid];
            if (l > -1) { atomicAdd(&nval_s, 1); if (l < CE) col_s[l] = 1.f; }
        }
        __syncthreads();
        float term = 0.f;
        if (tid < NF * CE) {
            int i = tid / CE, c = tid - i * CE;
            if (ego_labels[i] > -1) {
                float x = ego_preds[tid];
                float ep = 1.f / (1.f + expf(-x));
                ep = fminf(fmaxf(ep, 1e-7f), 1.f - 1e-7f);
                float oh = col_s[c];
                float af = 0.25f * oh + 0.75f * (1.f - oh);
                float pt = ep * oh + (1.f - ep) * (1.f - oh);
                float bce = -(oh * logf(ep) + (1.f - oh) * log1pf(-ep));
                float omp = 1.f - pt;
                term = bce * af * omp * omp;
            }
        }
#pragma unroll
        for (int o = 16; o > 0; o >>= 1) term += __shfl_down_sync(0xffffffffu, term, o);
        if (lane == 0) redc[wrp] = term;
        __syncthreads();
        if (tid == 0) {
            float esum = redc[0] + redc[1] + redc[2] + redc[3];
            int nval = nval_s;
            float ego = (nval > 0) ? esum / fmaxf((float)nval, 1.f) : 0.f;
            double cs = *((volatile double*)&g_cls_sum);
            double rs = *((volatile double*)&g_reg_sum);
            int pc = *((volatile int*)&g_pos_cnt);
            float np = fmaxf(1.f, (float)pc);
            if (out_size > 0) out[0] = (float)rs / (np * 4.f);
            if (out_size > 1) out[1] = ((float)cs / np) * 0.125f + ego * 0.25f;
            g_cls_sum = 0.0;
            g_reg_sum = 0.0;
            g_pos_cnt = 0;
            g_bar = 0u;
            g_tile = 0u;
        }
        for (int i = tid; i < NF * MM; i += THREADS) g_gt_key[i] = 0ull;
        __syncthreads();
        if (tid == 0) { __threadfence(); g_done = 0u; }
    }
}

extern "C" void kernel_launch(void* const* d_in, const int* in_sizes, int n_in,
                              void* d_out, int out_size) {
    (void)in_sizes; (void)n_in;
    const float* confidence   = (const float*)d_in[0];
    const float* pred_loc     = (const float*)d_in[1];
    const float* gt_boxes     = (const float*)d_in[2];
    const float* gt_labels    = (const float*)d_in[3];
    const int*   counts       = (const int*)d_in[4];
    const float* anchors      = (const float*)d_in[5];
    const float* ego_preds    = (const float*)d_in[6];
    const int*   ego_labels   = (const int*)d_in[7];
    const int*   cls_num_list = (const int*)d_in[8];
    float* out = (float*)d_out;

    fused_all<<<GRID, THREADS>>>(confidence, pred_loc, gt_boxes, gt_labels, counts,
                                 anchors, ego_preds, ego_labels, cls_num_list, out, out_size);
}